// round 12
// baseline (speedup 1.0000x reference)
#include <cuda_runtime.h>

// Casual_Conv1D: 31 chained Conv1d(1,1,k=2) == one 32-tap FIR + scalar bias.
// R12: split-K. Warp count was grid-capped at 4096 (R=16) -> occ 37% across
// all geometries. Split 32 taps into 2 groups of 16: group g = tid/64 computes
// taps [16g,16g+16) for the same 1024-output tile; partials summed at readout.
// 8192 warps total at unchanged instructions-per-output. TPB=128, TILE=1024.

#define B_    128
#define L_    16384
#define NL_   31
#define LOUT_ (L_ - NL_)          // 16353
#define TPB_  128
#define TILE_ 1024
#define PADN_ 1124                // inputs 1056, phys max 1120
#define PADO_ 1088                // per-group partials, phys max 1086

__global__ void __launch_bounds__(TPB_)
fir_kernel(const float* __restrict__ x, const float* __restrict__ W,
           const float* __restrict__ b, float* __restrict__ y) {
    __shared__ float sbuf[PADN_];        // input tile, pad-16: phys = i + i/16
    __shared__ float sout[2][PADO_];     // per-tap-group partial sums
    __shared__ float sc[33];             // 32 coefficients + bias at [32]

    const int tid   = threadIdx.x;
    const int row   = blockIdx.y;
    const int tile0 = blockIdx.x * TILE_;
    const float* xrow = x + (size_t)row * L_ + tile0;
    const bool last = (blockIdx.x == 15);        // tile0 = 15360

    // ---- issue all global loads first (latency overlaps compose) ----
    float4 v0 = *reinterpret_cast<const float4*>(xrow + tid * 4);
    float4 v1 = *reinterpret_cast<const float4*>(xrow + tid * 4 + 512);
    float4 ve;
    const bool edge = (tid < 8);
    if (edge)
        ve = last ? make_float4(0.f, 0.f, 0.f, 0.f)
                  : *reinterpret_cast<const float4*>(xrow + 1024 + tid * 4);

    // ---- warp 0: compose 31 k=2 filters while its LDGs are in flight ----
    if (tid < 32) {
        float c = (tid == 0) ? W[0] : ((tid == 1) ? W[1] : 0.0f);
        float d = b[0];
        #pragma unroll
        for (int i = 1; i < NL_; ++i) {
            const float w0 = W[2 * i], w1 = W[2 * i + 1];
            float cp = __shfl_up_sync(0xFFFFFFFFu, c, 1);
            if (tid == 0) cp = 0.0f;
            c = w0 * c + w1 * cp;
            d = (w0 + w1) * d + b[i];
        }
        sc[tid] = c;
        if (tid == 0) sc[32] = d;
    }

    // ---- stage tile: phys(4*tid + 512j + t) = 4*tid + tid/4 + 544j + t ----
    {
        float* sp = sbuf + tid * 4 + (tid >> 2);
        sp[0]   = v0.x; sp[1]   = v0.y; sp[2]   = v0.z; sp[3]   = v0.w;
        sp[544] = v1.x; sp[545] = v1.y; sp[546] = v1.z; sp[547] = v1.w;
    }
    if (edge) {   // phys(1024 + 4e + t) = 1088 + 4e + (e>>2) + t
        float* sp = sbuf + 1088 + tid * 4 + (tid >> 2);
        sp[0] = ve.x; sp[1] = ve.y; sp[2] = ve.z; sp[3] = ve.w;
    }
    __syncthreads();                             // barrier #1

    // ---- split-K FIR: group g computes taps [16g, 16g+16) of 16 outputs ---
    const int t64 = tid & 63;                    // output sub-tile owner
    const int g   = tid >> 6;                    // tap group 0 or 1
    // window element m' (0..30) at global idx 16*(t64+g)+m':
    //   phys = 17*(t64+g) + m' + (m'>>4)
    const float* sp = sbuf + (t64 + g) * 17;
#define XM(m_) sp[(m_) + ((m_) >> 4)]

    float r[16];
    #pragma unroll
    for (int t = 0; t < 16; ++t) r[t] = XM(t);

    const float bias = sc[32];
    float acc[16];
    {
        const float init = g ? 0.0f : bias;      // bias counted once
        #pragma unroll
        for (int j = 0; j < 16; ++j) acc[j] = init;
    }

    #pragma unroll
    for (int kk = 0; kk < 16; ++kk) {
        const float ck = sc[g * 16 + kk];        // LDS broadcast, imm offset
        #pragma unroll
        for (int j = 0; j < 16; ++j)
            acc[j] += ck * r[(kk + j) & 15];     // compile-time after unroll
        if (kk < 15)                             // refill slot with m' = kk+16
            r[kk & 15] = XM(kk + 16);
    }
#undef XM

    // ---- stage partials: phys(16*t64 + j) = 17*t64 + j (conflict-free) ----
    {
        float* so = sout[g] + t64 * 17;
        #pragma unroll
        for (int j = 0; j < 16; ++j)
            so[j] = acc[j];
    }
    __syncthreads();                             // barrier #2

    // ---- readout: i = tid + 128j, phys = tid + tid/16 + 136j; sum groups --
    float* yrow = y + (size_t)row * LOUT_ + tile0 + tid;
    const float* s0 = sout[0] + tid + (tid >> 4);
    const float* s1 = sout[1] + tid + (tid >> 4);
    if (!last) {
        #pragma unroll
        for (int j = 0; j < 8; ++j)
            yrow[j * 128] = s0[j * 136] + s1[j * 136];
    } else {
        const int nvalid = LOUT_ - tile0;        // 993
        #pragma unroll
        for (int j = 0; j < 8; ++j)
            if (tid + j * 128 < nvalid)
                yrow[j * 128] = s0[j * 136] + s1[j * 136];
    }
}

// ---------------------------------------------------------------------------
extern "C" void kernel_launch(void* const* d_in, const int* in_sizes, int n_in,
                              void* d_out, int out_size) {
    const float* x = (const float*)d_in[0];   // (128, 1, 16384) f32
    const float* W = (const float*)d_in[1];   // (31, 2) f32
    const float* b = (const float*)d_in[2];   // (31,)  f32
    float* y = (float*)d_out;                 // (128, 1, 16353) f32

    dim3 grid(L_ / TILE_, B_);                // (16, 128) = 2048 blocks
    fir_kernel<<<grid, TPB_>>>(x, W, b, y);
}

// round 13
// speedup vs baseline: 1.0156x; 1.0156x over previous
#include <cuda_runtime.h>

// Casual_Conv1D: 31 chained Conv1d(1,1,k=2) == one 32-tap FIR + scalar bias.
// R13: warp-autonomous tiles — ZERO block barriers. Occupancy experiments
// (occ 37->58%) left dur flat: warps are gang-stalled at __syncthreads, not
// starved. Each warp owns a 512-output tile + private smem chunk (inputs,
// its own coef copy, output staging); only __syncwarp inside. Scalar ring
// FIR, imm-offset pad-16 addressing, coalesced scalar readout.

#define B_    128
#define L_    16384
#define NL_   31
#define LOUT_ (L_ - NL_)          // 16353
#define TPB_  128
#define WTILE_ 512                // outputs per warp

__global__ void __launch_bounds__(TPB_)
fir_kernel(const float* __restrict__ x, const float* __restrict__ W,
           const float* __restrict__ b, float* __restrict__ y) {
    // per-warp chunks: [0,576) input phys (543 in), [576,608) coefs, [608] bias
    __shared__ float sin_[4][612];
    __shared__ float sout_[4][544];   // 512 outputs, phys = 17*lane + j

    const int lane = threadIdx.x & 31;
    const int w    = threadIdx.x >> 5;
    const int row  = blockIdx.y;
    const int bx   = blockIdx.x;
    const int wtile0 = bx * 2048 + w * WTILE_;        // warp's first output
    const float* xw = x + (size_t)row * L_ + wtile0;
    const bool lastw = (bx == 7) && (w == 3);         // only OOB-halo warp

    // ---- issue this warp's global loads (latency overlaps compose) ----
    // body [0,512): max global idx = wtile0 + 511 <= 16383, always safe.
    float4 v[4];
    #pragma unroll
    for (int j = 0; j < 4; ++j)
        v[j] = *reinterpret_cast<const float4*>(xw + 4 * lane + 128 * j);
    float4 ve;
    if (lane < 8)
        ve = lastw ? make_float4(0.f, 0.f, 0.f, 0.f)
                   : *reinterpret_cast<const float4*>(xw + 512 + 4 * lane);

    // ---- per-warp filter composition (31-step shfl chain) ----
    float c = (lane == 0) ? W[0] : ((lane == 1) ? W[1] : 0.0f);
    float d = b[0];
    #pragma unroll
    for (int i = 1; i < NL_; ++i) {
        const float w0 = W[2 * i], w1 = W[2 * i + 1];
        float cp = __shfl_up_sync(0xFFFFFFFFu, c, 1);
        if (lane == 0) cp = 0.0f;
        c = w0 * c + w1 * cp;
        d = (w0 + w1) * d + b[i];
    }

    // ---- stage into this warp's chunk; imm-offset pad-16 addressing ----
    float* si = sin_[w];
    {   // phys(4*lane + 128j + t) = 4*lane + lane/4 + 136j + t
        float* sp = si + 4 * lane + (lane >> 2);
        #pragma unroll
        for (int j = 0; j < 4; ++j) {
            sp[136 * j + 0] = v[j].x;
            sp[136 * j + 1] = v[j].y;
            sp[136 * j + 2] = v[j].z;
            sp[136 * j + 3] = v[j].w;
        }
    }
    if (lane < 8) {   // phys(512 + 4e + t) = 544 + 4e + e/4 + t
        float* sp = si + 544 + 4 * lane + (lane >> 2);
        sp[0] = ve.x; sp[1] = ve.y; sp[2] = ve.z; sp[3] = ve.w;
    }
    si[576 + lane] = c;
    if (lane == 0) si[608] = d;
    __syncwarp();

    // ---- scalar rolling-ring FIR: 16 outputs/lane ----
    // o0 = 16*lane; phys(o0+m) = 17*lane + m + m/16 (conflict-free)
    const float* sp = si + lane * 17;
#define XM(m_) sp[(m_) + ((m_) >> 4)]

    float r[16];
    #pragma unroll
    for (int t = 0; t < 16; ++t) r[t] = XM(t);

    const float bias = si[608];
    float acc[16];
    #pragma unroll
    for (int j = 0; j < 16; ++j) acc[j] = bias;

    #pragma unroll
    for (int k = 0; k < 32; ++k) {
        const float ck = si[576 + k];            // LDS broadcast, imm offset
        #pragma unroll
        for (int j = 0; j < 16; ++j)
            acc[j] += ck * r[(k + j) & 15];      // compile-time after unroll
        if (k < 31)                              // refill slot with t = k+16
            r[k & 15] = XM(k + 16);
    }
#undef XM

    // ---- stage outputs: phys(16*lane + j) = 17*lane + j ----
    {
        float* so = sout_[w] + lane * 17;
        #pragma unroll
        for (int j = 0; j < 16; ++j)
            so[j] = acc[j];
    }
    __syncwarp();

    // ---- coalesced scalar readout: i = lane + 32j, phys = i + i/16 ----
    float* yw = y + (size_t)row * LOUT_ + wtile0 + lane;
    const float* sr = sout_[w] + lane + (lane >> 4);
    const int nvalid = LOUT_ - wtile0;           // >= 512 except last warp
    if (nvalid >= WTILE_) {
        #pragma unroll
        for (int j = 0; j < 16; ++j)
            yw[j * 32] = sr[j * 34];
    } else {                                     // last warp: nvalid = 481
        #pragma unroll
        for (int j = 0; j < 16; ++j)
            if (lane + j * 32 < nvalid)
                yw[j * 32] = sr[j * 34];
    }
}

// ---------------------------------------------------------------------------
extern "C" void kernel_launch(void* const* d_in, const int* in_sizes, int n_in,
                              void* d_out, int out_size) {
    const float* x = (const float*)d_in[0];   // (128, 1, 16384) f32
    const float* W = (const float*)d_in[1];   // (31, 2) f32
    const float* b = (const float*)d_in[2];   // (31,)  f32
    float* y = (float*)d_out;                 // (128, 1, 16353) f32

    dim3 grid(8, B_);                         // 1024 blocks, 4096 warps
    fir_kernel<<<grid, TPB_>>>(x, W, b, y);
}